// round 7
// baseline (speedup 1.0000x reference)
#include <cuda_runtime.h>
#include <math_constants.h>

#define NPTS  4096
#define NB    4
#define KNN   16
#define DFEAT 64
#define DOUT  128
#define CH_STRIDE 65536   // NPTS*KNN
#define CHUNK 2048        // KNN smem chunk (32KB of float4)
#define GRP   64          // candidates scanned per interleaved feature store

// Scratch (device globals; no allocation allowed)
__device__ float4 g_coords4[NB * NPTS];          // (x,y,z,|c|^2)
__device__ int    g_idx [NB * NPTS * KNN];
__device__ float  g_dist[NB * NPTS * KNN];

// ---------------------------------------------------------------------------
// Kernel A: pack coords into float4 with precomputed squared norm
// ---------------------------------------------------------------------------
__global__ void build_coords4_k(const float* __restrict__ coords) {
    int p = blockIdx.x * blockDim.x + threadIdx.x;
    if (p < NB * NPTS) {
        float x = coords[3 * p + 0];
        float y = coords[3 * p + 1];
        float z = coords[3 * p + 2];
        float sq = fmaf(z, z, fmaf(y, y, x * x));
        g_coords4[p] = make_float4(x, y, z, sq);
    }
}

// ---------------------------------------------------------------------------
// Kernel B: exact KNN (K=16), one thread per query, candidates in two 2048-pt
// smem chunks (32KB static). Sort key: key_c = |c|^2 - 2*dot(q,c) == d2-|q|^2
// (per-thread const offset -> identical ordering). Stable tie-break:
// ascending-j scan + strict '<' bubble == lax.top_k (ascending d2, smaller
// index first). Final dist sqrt(max(q.w+key,1e-12)) == ref.
//
// FUSED: the 64 KNN-independent feature-broadcast channels of the output are
// written here, one channel per 64-candidate scan group, so their 67MB of
// store traffic drains under the scan's compute time instead of serializing
// in out_k. Feature value is prefetched one group ahead (rolling register).
// ---------------------------------------------------------------------------
__global__ void __launch_bounds__(128) knn_k(const float* __restrict__ features,
                                             float* __restrict__ out) {
    __shared__ float4 sc[CHUNK];
    int b  = blockIdx.x >> 5;                       // 32 blocks per batch
    int qi = ((blockIdx.x & 31) << 7) + threadIdx.x;

    const float4* cb = g_coords4 + b * NPTS;
    float4 q = cb[qi];

    // feature-channel pointers for this query
    const float* fp = features + b * DFEAT * NPTS + qi;           // [d*NPTS]
    float* op = out + (b * 192 + DOUT) * CH_STRIDE + qi * KNN;    // [d*CH_STRIDE]

    float bd[KNN];   // keys (d2 - q.w)
    int   bj[KNN];
#pragma unroll
    for (int s = 0; s < KNN; s++) { bd[s] = CUDART_INF_F; bj[s] = 0; }

    for (int half = 0; half < 2; half++) {
        int j0 = half * CHUNK;
        __syncthreads();
        for (int p = threadIdx.x; p < CHUNK; p += 128) sc[p] = cb[j0 + p];
        __syncthreads();

        int d0 = half * 32;                 // 32 feature channels per chunk
        float f = fp[d0 * NPTS];            // prefetch first channel value

        for (int g = 0; g < 32; g++) {
            float fcur = f;
            if (g + 1 < 32) f = fp[(d0 + g + 1) * NPTS];   // prefetch next

            int jb = g * GRP;
#pragma unroll 8
            for (int jl = jb; jl < jb + GRP; jl++) {
                float4 c = sc[jl];
                float dot = fmaf(q.z, c.z, fmaf(q.y, c.y, q.x * c.x));
                float key = fmaf(-2.0f, dot, c.w);
                if (key < bd[KNN - 1]) {            // rare (~90/4096)
                    bd[KNN - 1] = key;
                    bj[KNN - 1] = j0 + jl;
#pragma unroll
                    for (int s = KNN - 1; s > 0; --s) {
                        if (bd[s] < bd[s - 1]) {
                            float td = bd[s]; bd[s] = bd[s - 1]; bd[s - 1] = td;
                            int   tj = bj[s]; bj[s] = bj[s - 1]; bj[s - 1] = tj;
                        }
                    }
                }
            }

            // interleaved feature store: channel d0+g, 16 k-values (4xSTG.128)
            float4 v = make_float4(fcur, fcur, fcur, fcur);
            float4* o = (float4*)(op + (d0 + g) * CH_STRIDE);
            o[0] = v; o[1] = v; o[2] = v; o[3] = v;
        }
    }

    // vectorized top-k writeback: 4x int4 + 4x float4 (STG.128)
    int base = (b * NPTS + qi) * KNN;
#pragma unroll
    for (int v4 = 0; v4 < KNN / 4; v4++) {
        int4 iv = make_int4(bj[v4 * 4 + 0], bj[v4 * 4 + 1],
                            bj[v4 * 4 + 2], bj[v4 * 4 + 3]);
        float4 dv = make_float4(sqrtf(fmaxf(q.w + bd[v4 * 4 + 0], 1e-12f)),
                                sqrtf(fmaxf(q.w + bd[v4 * 4 + 1], 1e-12f)),
                                sqrtf(fmaxf(q.w + bd[v4 * 4 + 2], 1e-12f)),
                                sqrtf(fmaxf(q.w + bd[v4 * 4 + 3], 1e-12f)));
        *(int4*)  (g_idx  + base + v4 * 4) = iv;
        *(float4*)(g_dist + base + v4 * 4) = dv;
    }
}

// ---------------------------------------------------------------------------
// Kernel C: encoding + 1x1-conv MLP (128 channels; feature channels already
// written by knn_k). Factored weights:
//   r_c = (Wa+Wc)·pi + (Wb−Wc)·pj + w9·d + b  (u = Wa+Wc, v = Wb−Wc)
// Per channel: 2 x LDS.128 (u0..2,v0 | v1,v2,w9,b), base = u·pi + b shared
// across the k-quad (3 FMA), then 4 FMA per k. 19 FMA/channel vs 40 naive.
// All stores STG.128, warp-contiguous 512B per channel row.
// ---------------------------------------------------------------------------
__global__ void __launch_bounds__(128) out_k(const float* __restrict__ W,
                                             const float* __restrict__ bias,
                                             float* __restrict__ out) {
    __shared__ float sW[DOUT * 8];   // per ch: u0,u1,u2,v0, v1,v2,w9,b
    int t = threadIdx.x;
    for (int c = t; c < DOUT; c += 128) {
        const float* w = W + c * 10;   // [pi0..2, pj0..2, dp0..2, d]
        sW[c * 8 + 0] = w[0] + w[6];   // u0
        sW[c * 8 + 1] = w[1] + w[7];   // u1
        sW[c * 8 + 2] = w[2] + w[8];   // u2
        sW[c * 8 + 3] = w[3] - w[6];   // v0
        sW[c * 8 + 4] = w[4] - w[7];   // v1
        sW[c * 8 + 5] = w[5] - w[8];   // v2
        sW[c * 8 + 6] = w[9];          // w9
        sW[c * 8 + 7] = bias[c];       // b
    }
    __syncthreads();

    int tid = blockIdx.x * 128 + t;
    int k4  = tid & 3;                 // k-quad (0..3)
    int n   = (tid >> 2) & (NPTS - 1);
    int b   = tid >> 14;

    float4 pi = g_coords4[b * NPTS + n];

    int base = (b * NPTS + n) * KNN + k4 * 4;
    int4   jj = *(const int4*)  (g_idx  + base);
    float4 dd = *(const float4*)(g_dist + base);

    float4 pj0 = g_coords4[b * NPTS + jj.x];
    float4 pj1 = g_coords4[b * NPTS + jj.y];
    float4 pj2 = g_coords4[b * NPTS + jj.z];
    float4 pj3 = g_coords4[b * NPTS + jj.w];

    int ob = b * 192 * CH_STRIDE + n * KNN + k4 * 4;

#pragma unroll 4
    for (int c = 0; c < DOUT; c++) {
        float4 wa = *(const float4*)(sW + c * 8);      // u0,u1,u2,v0
        float4 wb = *(const float4*)(sW + c * 8 + 4);  // v1,v2,w9,b
        // base = u·pi + b  (shared across the quad)
        float bse = fmaf(wa.z, pi.z, fmaf(wa.y, pi.y, fmaf(wa.x, pi.x, wb.w)));
        float4 r;
        r.x = fmaf(wb.z, dd.x, fmaf(wb.y, pj0.z, fmaf(wb.x, pj0.y, fmaf(wa.w, pj0.x, bse))));
        r.y = fmaf(wb.z, dd.y, fmaf(wb.y, pj1.z, fmaf(wb.x, pj1.y, fmaf(wa.w, pj1.x, bse))));
        r.z = fmaf(wb.z, dd.z, fmaf(wb.y, pj2.z, fmaf(wb.x, pj2.y, fmaf(wa.w, pj2.x, bse))));
        r.w = fmaf(wb.z, dd.w, fmaf(wb.y, pj3.z, fmaf(wb.x, pj3.y, fmaf(wa.w, pj3.x, bse))));
        *(float4*)(out + ob + c * CH_STRIDE) = r;
    }
}

// ---------------------------------------------------------------------------
extern "C" void kernel_launch(void* const* d_in, const int* in_sizes, int n_in,
                              void* d_out, int out_size) {
    const float* coords   = (const float*)d_in[0];
    const float* features = (const float*)d_in[1];
    const float* W        = (const float*)d_in[2];
    const float* bias     = (const float*)d_in[3];
    float* out = (float*)d_out;

    build_coords4_k<<<(NB * NPTS + 255) / 256, 256>>>(coords);
    knn_k<<<NB * 32, 128>>>(features, out);
    out_k<<<(NB * NPTS * 4) / 128, 128>>>(W, bias, out);
}